// round 14
// baseline (speedup 1.0000x reference)
#include <cuda_runtime.h>
#include <cuda_bf16.h>

#define NN 10000
#define EE 100000
#define W  32
#define CHMAX 24576

typedef unsigned long long u64;

__device__ __forceinline__ u64 pk2(float x, float y) {
    u64 r; asm("mov.b64 %0,{%1,%2};" : "=l"(r) : "f"(x), "f"(y)); return r;
}
__device__ __forceinline__ void fma2(u64& d, u64 a, u64 b) {
    asm("fma.rn.f32x2 %0,%1,%2,%0;" : "+l"(d) : "l"(a), "l"(b));
}
__device__ __forceinline__ float2 up2(u64 v) {
    float2 f; asm("mov.b64 {%0,%1},%2;" : "=f"(f.x), "=f"(f.y) : "l"(v)); return f;
}
__device__ __forceinline__ u64 add2(u64 a, u64 b) {
    u64 r; asm("add.rn.f32x2 %0,%1,%2;" : "=l"(r) : "l"(a), "l"(b)); return r;
}

// ---------------- scratch ----------------
__device__ float g_h[NN * W];
__device__ float g_coord[NN * 3];
__device__ float g_G[(size_t)NN * 4096];   // G[n][c*32+i]  (c-major)
__device__ float g_W3p[32 * 4096];         // W3p[j][c*32+i] = ker_w3[c][i*32+j]
__device__ float g_Bh[NN * W];
__device__ float g_msum[NN * W];
__device__ float g_csum[NN * 3];
__device__ int   g_degi[NN];
__device__ int   g_cnt[NN];
__device__ int   g_offs[NN + 1];
__device__ int   g_cur[NN];
__device__ int   g_srow[EE];
__device__ int   g_scol[EE];
__device__ float g_sea[EE * 6];
__device__ float g_k2[(size_t)EE * 128];
__device__ int   g_chcnt[NN];
__device__ int   g_choffs[NN + 1];
__device__ int   g_chv[CHMAX], g_che[CHMAX], g_chc[CHMAX];
__device__ int   g_nch;

// ---------------- setup ----------------

__global__ void k_w3p(const float* __restrict__ kw3) {
    int idx = blockIdx.x * blockDim.x + threadIdx.x;
    if (idx < 128 * 1024) {
        int c = idx >> 10, rem = idx & 1023, i = rem >> 5, j = rem & 31;
        g_W3p[j * 4096 + c * 32 + i] = kw3[idx];
    }
}

__global__ void k_zero_hist(int n) {
    int idx = blockIdx.x * blockDim.x + threadIdx.x;
    if (idx < n) { g_cnt[idx] = 0; g_degi[idx] = 0; }
}

__global__ void k_init(const float* __restrict__ x, const float* __restrict__ coords,
                       const float* __restrict__ fc1w, const float* __restrict__ fc1b,
                       const int* __restrict__ ei, int n, int e) {
    int idx = blockIdx.x * blockDim.x + threadIdx.x;
    if (idx < n * W) {
        int node = idx >> 5, i = idx & 31;
        float acc = fc1b[i];
#pragma unroll
        for (int j = 0; j < 3; j++) acc += x[node * 3 + j] * fc1w[j * W + i];
        g_h[idx] = acc;
    }
    if (idx < n * 3) g_coord[idx] = coords[idx];
    if (idx < e) {
        atomicAdd(&g_cnt[ei[e + idx]], 1);
        atomicAdd(&g_degi[ei[idx]], 1);
    }
}

__global__ __launch_bounds__(1024) void k_scan(int n) {
    __shared__ int ts[1024];
    int tid = threadIdx.x;
    int per = (n + 1023) / 1024;
    int base = tid * per;
    int s = 0;
    for (int i = 0; i < per; i++) { int idx = base + i; if (idx < n) s += g_cnt[idx]; }
    ts[tid] = s;
    __syncthreads();
    for (int off = 1; off < 1024; off <<= 1) {
        int v = (tid >= off) ? ts[tid - off] : 0;
        __syncthreads();
        ts[tid] += v;
        __syncthreads();
    }
    int run = (tid > 0) ? ts[tid - 1] : 0;
    for (int i = 0; i < per; i++) {
        int idx = base + i;
        if (idx < n) { int cv = g_cnt[idx]; g_offs[idx] = run; g_cur[idx] = run; run += cv; }
    }
    if (tid == 1023) g_offs[n] = run;
}

__global__ void k_scatter(const int* __restrict__ ei, const float* __restrict__ ea, int e) {
    int idx = blockIdx.x * blockDim.x + threadIdx.x;
    if (idx >= e) return;
    int c = ei[e + idx];
    int p = atomicAdd(&g_cur[c], 1);
    g_srow[p] = ei[idx];
    g_scol[p] = c;
#pragma unroll
    for (int a = 0; a < 6; a++) g_sea[p * 6 + a] = ea[idx * 6 + a];
}

__global__ void k_chprep(int n) {
    int v = blockIdx.x * blockDim.x + threadIdx.x;
    if (v < n) {
        int d = g_offs[v + 1] - g_offs[v];
        g_chcnt[v] = (d + 7) >> 3;
    }
}

__global__ __launch_bounds__(1024) void k_chscan(int n) {
    __shared__ int ts[1024];
    int tid = threadIdx.x;
    int per = (n + 1023) / 1024;
    int base = tid * per;
    int s = 0;
    for (int i = 0; i < per; i++) { int idx = base + i; if (idx < n) s += g_chcnt[idx]; }
    ts[tid] = s;
    __syncthreads();
    for (int off = 1; off < 1024; off <<= 1) {
        int v = (tid >= off) ? ts[tid - off] : 0;
        __syncthreads();
        ts[tid] += v;
        __syncthreads();
    }
    int run = (tid > 0) ? ts[tid - 1] : 0;
    for (int i = 0; i < per; i++) {
        int idx = base + i;
        if (idx < n) { int cv = g_chcnt[idx]; g_choffs[idx] = run; run += cv; }
    }
    if (tid == 1023) { g_choffs[n] = run; g_nch = run; }
}

__global__ void k_chfill(int n) {
    int v = blockIdx.x * blockDim.x + threadIdx.x;
    if (v >= n) return;
    int base = g_choffs[v], nc = g_chcnt[v];
    int s0 = g_offs[v], d = g_offs[v + 1] - s0;
    for (int k = 0; k < nc; k++) {
        g_chv[base + k] = v;
        g_che[base + k] = s0 + 8 * k;
        int rem = d - 8 * k;
        g_chc[base + k] = rem > 8 ? 8 : rem;
    }
}

// ---------------- per-depth ----------------

// G[n][c*32+i] = h[n][:] @ W3p ; pair-over-K FFMA2, 32 nodes x 128 cols/block
__global__ __launch_bounds__(256, 4) void k_G(int n) {
    __shared__ float hs[32 * 32];     // 4KB
    __shared__ u64   bs2[16 * 128];   // 16KB  (K-pairs interleaved)
    const int tid = threadIdx.x;
    const int n0 = blockIdx.x * 32;
    const int q0 = blockIdx.y * 128;
    for (int i = tid; i < 1024; i += 256) {
        int nn = i >> 5, j = i & 31;
        int node = n0 + nn;
        hs[i] = (node < n) ? g_h[node * 32 + j] : 0.0f;
    }
    for (int i = tid; i < 2048; i += 256) {
        int j2 = i >> 7, col = i & 127;
        bs2[i] = pk2(g_W3p[(2 * j2) * 4096 + q0 + col],
                     g_W3p[(2 * j2 + 1) * 4096 + q0 + col]);
    }
    __syncthreads();
    const int ty = tid >> 5, tx = tid & 31;
    const u64 zz = pk2(0.f, 0.f);
    u64 acc[4][4];
#pragma unroll
    for (int r = 0; r < 4; r++)
#pragma unroll
        for (int s = 0; s < 4; s++) acc[r][s] = zz;
#pragma unroll
    for (int j2 = 0; j2 < 16; j2++) {
        ulonglong2 b01 = *(const ulonglong2*)&bs2[j2 * 128 + tx * 4];
        ulonglong2 b23 = *(const ulonglong2*)&bs2[j2 * 128 + tx * 4 + 2];
#pragma unroll
        for (int r = 0; r < 4; r++) {
            u64 a2 = *(const u64*)&hs[(ty * 4 + r) * 32 + 2 * j2];
            fma2(acc[r][0], a2, b01.x);
            fma2(acc[r][1], a2, b01.y);
            fma2(acc[r][2], a2, b23.x);
            fma2(acc[r][3], a2, b23.y);
        }
    }
#pragma unroll
    for (int r = 0; r < 4; r++) {
        int node = n0 + ty * 4 + r;
        if (node < n) {
            float4 o;
            float2 f0 = up2(acc[r][0]); o.x = f0.x + f0.y;
            float2 f1 = up2(acc[r][1]); o.y = f1.x + f1.y;
            float2 f2 = up2(acc[r][2]); o.z = f2.x + f2.y;
            float2 f3 = up2(acc[r][3]); o.w = f3.x + f3.y;
            *(float4*)&g_G[(size_t)node * 4096 + q0 + tx * 4] = o;
        }
    }
}

// edge MLP (layers 1+2), pair-over-K FFMA2, 32 edges x 128 outs/block
#define M2W2P 0        // u64[32*128] -> 8192 floats
#define M2K1S 8192     // 32*66 = 2112
#define M2EAS 10304    // 32*9 = 288
#define M2W1S 10592    // 448
#define M2B1S 11040    // 64
#define M2TOT 11104    // *4 = 44416 bytes
__global__ __launch_bounds__(256, 3) void k_mlp(const float* __restrict__ kw1,
                                                const float* __restrict__ kb1,
                                                const float* __restrict__ kw2,
                                                const float* __restrict__ kb2, int e) {
    extern __shared__ float sm[];
    u64* w2p = (u64*)sm;
    const int tid = threadIdx.x;
    const int e0 = blockIdx.x * 32;

    for (int i = tid; i < 4096; i += 256) {
        int j2 = i >> 7, col = i & 127;
        w2p[i] = pk2(kw2[(2 * j2) * 128 + col], kw2[(2 * j2 + 1) * 128 + col]);
    }
    for (int i = tid; i < 448; i += 256) sm[M2W1S + i] = kw1[i];
    if (tid < 64) sm[M2B1S + tid] = kb1[tid];
    for (int i = tid; i < 192; i += 256) {
        int ed = i / 6, a = i - ed * 6;
        sm[M2EAS + ed * 9 + a] = g_sea[(size_t)(e0 + ed) * 6 + a];
    }
    if (tid < 32) {
        int ed = e0 + tid;
        int r = g_srow[ed], c = g_scol[ed];
        float rad = 0.0f;
#pragma unroll
        for (int d = 0; d < 3; d++) {
            float dd = g_coord[r * 3 + d] - g_coord[c * 3 + d];
            rad += dd * dd;
        }
        sm[M2EAS + tid * 9 + 6] = rad;
    }
    __syncthreads();

    // layer 1: 32 edges x 64 outs, 8 outs/thread
    {
        int ed = tid >> 3, q = tid & 7;
        float ea[7];
#pragma unroll
        for (int a = 0; a < 7; a++) ea[a] = sm[M2EAS + ed * 9 + a];
#pragma unroll
        for (int jj = 0; jj < 8; jj++) {
            int c = q * 8 + jj;
            float acc = sm[M2B1S + c];
#pragma unroll
            for (int a = 0; a < 7; a++) acc += ea[a] * sm[M2W1S + a * 64 + c];
            sm[M2K1S + ed * 66 + c] = fmaxf(acc, 0.0f);
        }
    }
    __syncthreads();

    // layer 2: pair-K GEMM 32x128, K=64
    const int ty = tid >> 5, tx = tid & 31;
    const u64 zz = pk2(0.f, 0.f);
    u64 acc[4][4];
#pragma unroll
    for (int r = 0; r < 4; r++)
#pragma unroll
        for (int s = 0; s < 4; s++) acc[r][s] = zz;
#pragma unroll 8
    for (int j2 = 0; j2 < 32; j2++) {
        ulonglong2 b01 = *(const ulonglong2*)&w2p[j2 * 128 + tx * 4];
        ulonglong2 b23 = *(const ulonglong2*)&w2p[j2 * 128 + tx * 4 + 2];
#pragma unroll
        for (int r = 0; r < 4; r++) {
            u64 a2 = *(const u64*)&sm[M2K1S + (ty * 4 + r) * 66 + 2 * j2];
            fma2(acc[r][0], a2, b01.x);
            fma2(acc[r][1], a2, b01.y);
            fma2(acc[r][2], a2, b23.x);
            fma2(acc[r][3], a2, b23.y);
        }
    }
    float4 bb = *(const float4*)&kb2[tx * 4];
#pragma unroll
    for (int r = 0; r < 4; r++) {
        int ed = e0 + ty * 4 + r;
        float4 o;
        float2 f0 = up2(acc[r][0]); o.x = fmaxf(f0.x + f0.y + bb.x, 0.f);
        float2 f1 = up2(acc[r][1]); o.y = fmaxf(f1.x + f1.y + bb.y, 0.f);
        float2 f2 = up2(acc[r][2]); o.z = fmaxf(f2.x + f2.y + bb.z, 0.f);
        float2 f3 = up2(acc[r][3]); o.w = fmaxf(f3.x + f3.y + bb.w, 0.f);
        if (ed < e) *(float4*)&g_k2[(size_t)ed * 128 + tx * 4] = o;
    }
}

// Bh + accumulator zeroing fused
__global__ void k_Bh(const float* __restrict__ kb3, int n) {
    int idx = blockIdx.x * blockDim.x + threadIdx.x;
    if (idx < n * 3) g_csum[idx] = 0.0f;
    if (idx >= n * W) return;
    g_msum[idx] = 0.0f;
    int node = idx >> 5, i = idx & 31;
    float acc = 0.0f;
#pragma unroll
    for (int j = 0; j < 32; j++) acc += kb3[i * 32 + j] * g_h[node * 32 + j];
    g_Bh[idx] = acc;
}

// chunked edge kernel: warp per <=8-edge same-col chunk
#define SCM1P 0       // 1024 (cmw1 pairs)
#define SCMB  1024    // 32
#define SCMW  1056    // 32
#define SK2P  1088    // 8 warps * 1024 floats (64 c-pairs x 8 edges as u64)
#define SMSB  9280    // 8 warps * 256
#define SETOT 11328   // *4 = 45312 bytes
__global__ __launch_bounds__(256) void k_edge(const float* __restrict__ cmw1,
                                              const float* __restrict__ cmb1,
                                              const float* __restrict__ cmw2) {
    extern __shared__ float sm[];
    const int tid = threadIdx.x, w = tid >> 5, lane = tid & 31;

    for (int i = tid; i < 1024; i += 256) {
        int i2 = i >> 6, r = i & 63, ln = r >> 1, p = r & 1;
        sm[SCM1P + i] = cmw1[(2 * i2 + p) * 32 + ln];
    }
    if (tid < 32) { sm[SCMB + tid] = cmb1[tid]; sm[SCMW + tid] = cmw2[tid]; }
    __syncthreads();

    u64* K2 = (u64*)(sm + SK2P + w * 1024);   // [c2][s]
    float* msb = sm + SMSB + w * 256;
    const u64 zz = pk2(0.f, 0.f);

    const int TW = gridDim.x * 8;
    const int nch = g_nch;
    for (int ci = blockIdx.x * 8 + w; ci < nch; ci += TW) {
        const int v = g_chv[ci], e0 = g_che[ci], cnt = g_chc[ci];

        {
            int s = lane >> 2, f = lane & 3;
            bool valid = (s < cnt);
#pragma unroll
            for (int t = 0; t < 8; t++) {
                int cb = (t * 4 + f) * 4;
                float4 vv = valid ? *(const float4*)&g_k2[(size_t)(e0 + s) * 128 + cb]
                                  : make_float4(0.f, 0.f, 0.f, 0.f);
                K2[(cb >> 1) * 8 + s]       = pk2(vv.x, vv.y);
                K2[((cb >> 1) + 1) * 8 + s] = pk2(vv.z, vv.w);
            }
        }
        int rl = (lane < cnt) ? g_srow[e0 + lane] : 0;
        float cv = (lane < 3) ? g_coord[v * 3 + lane] : 0.0f;
        float bh = g_Bh[v * 32 + lane];
        __syncwarp();

        const float* gB = g_G + (size_t)v * 4096;
        u64 mm[8];
#pragma unroll
        for (int s = 0; s < 8; s++) mm[s] = zz;
        float ga = gB[lane], gb = gB[32 + lane];
#pragma unroll 4
        for (int c2 = 0; c2 < 64; c2++) {
            u64 gg = pk2(ga, gb);
            if (c2 < 63) { ga = gB[(c2 + 1) * 64 + lane]; gb = gB[(c2 + 1) * 64 + 32 + lane]; }
#pragma unroll
            for (int s = 0; s < 8; s++) fma2(mm[s], K2[c2 * 8 + s], gg);
        }
        float mreg[8];
#pragma unroll
        for (int s = 0; s < 8; s++) {
            float2 f2 = up2(mm[s]);
            mreg[s] = f2.x + f2.y + bh;
            msb[s * 32 + lane] = mreg[s];
        }
        __syncwarp();

        for (int s = 0; s < cnt; s++) {
            u64 ta = zz, tb = zz;
#pragma unroll
            for (int i2 = 0; i2 < 16; i2 += 2) {
                u64 mp0 = *(const u64*)&msb[s * 32 + i2 * 2];
                u64 mp1 = *(const u64*)&msb[s * 32 + i2 * 2 + 2];
                u64 wp0 = *(const u64*)&sm[SCM1P + i2 * 64 + lane * 2];
                u64 wp1 = *(const u64*)&sm[SCM1P + (i2 + 1) * 64 + lane * 2];
                fma2(ta, mp0, wp0);
                fma2(tb, mp1, wp1);
            }
            float2 tf = up2(add2(ta, tb));
            float tac = fmaxf(sm[SCMB + lane] + tf.x + tf.y, 0.0f);
            float ph = tac * sm[SCMW + lane];
#pragma unroll
            for (int o = 16; o; o >>= 1) ph += __shfl_xor_sync(0xffffffffu, ph, o);

            int r = __shfl_sync(0xffffffffu, rl, s);
            atomicAdd(&g_msum[r * 32 + lane], mreg[s]);
            if (lane < 3) {
                float cdl = g_coord[r * 3 + lane] - cv;
                atomicAdd(&g_csum[r * 3 + lane], cdl * ph);
            }
        }
        __syncwarp();
    }
}

__global__ void k_update(int n) {
    int idx = blockIdx.x * blockDim.x + threadIdx.x;
    if (idx >= n * W) return;
    int node = idx >> 5, i = idx & 31;
    int d = g_degi[node];
    float inv = 1.0f / (float)(d > 1 ? d : 1);
    g_h[idx] = fmaxf(g_h[idx] + g_msum[idx] * inv, 0.0f);
    if (i < 3) g_coord[node * 3 + i] += g_csum[node * 3 + i] * inv;
}

__global__ __launch_bounds__(256) void k_out(const float* __restrict__ fw1,
                                             const float* __restrict__ fb1,
                                             const float* __restrict__ fw2,
                                             const float* __restrict__ fb2,
                                             float* __restrict__ dout, int n) {
    int gw = (blockIdx.x * blockDim.x + threadIdx.x) >> 5;
    int lane = threadIdx.x & 31;
    if (gw >= n) return;
    const int node = gw;
    float hm = g_h[node * 32 + lane];
    float t0 = fb1[lane], t1 = fb1[lane + 32];
#pragma unroll
    for (int i = 0; i < 32; i++) {
        float hh = __shfl_sync(0xffffffffu, hm, i);
        t0 += hh * fw1[i * 64 + lane];
        t1 += hh * fw1[i * 64 + lane + 32];
    }
    t0 = fmaxf(t0, 0.0f);
    t1 = fmaxf(t1, 0.0f);
    float part = t0 * fw2[lane] + t1 * fw2[32 + lane];
#pragma unroll
    for (int o = 16; o; o >>= 1) part += __shfl_xor_sync(0xffffffffu, part, o);
    if (lane == 0) dout[node] = part + fb2[0];
    if (lane < 3) dout[n + node * 3 + lane] = g_coord[node * 3 + lane];
}

// ---------------- host launcher ----------------
extern "C" void kernel_launch(void* const* d_in, const int* in_sizes, int n_in,
                              void* d_out, int out_size) {
    const float* x      = (const float*)d_in[0];
    const int*   ei     = (const int*)  d_in[1];
    const float* eattr  = (const float*)d_in[2];
    const float* coords = (const float*)d_in[3];
    const float* fc1w   = (const float*)d_in[4];
    const float* fc1b   = (const float*)d_in[5];
    const float* kw1    = (const float*)d_in[6];
    const float* kb1    = (const float*)d_in[7];
    const float* kw2    = (const float*)d_in[8];
    const float* kb2    = (const float*)d_in[9];
    const float* kw3    = (const float*)d_in[10];
    const float* kb3    = (const float*)d_in[11];
    const float* cmw1   = (const float*)d_in[12];
    const float* cmb1   = (const float*)d_in[13];
    const float* cmw2   = (const float*)d_in[14];
    const float* fw1    = (const float*)d_in[15];
    const float* fb1    = (const float*)d_in[16];
    const float* fw2    = (const float*)d_in[17];
    const float* fb2    = (const float*)d_in[18];
    float* dout = (float*)d_out;

    int n = in_sizes[0] / 3;   // 10000
    int e = in_sizes[1] / 2;   // 100000
    if (n > NN) n = NN;
    if (e > EE) e = EE;

    const int T = 256;
    int gn32 = (n * W + T - 1) / T;
    int gE   = (e + T - 1) / T;
    size_t smem_mlp  = (size_t)M2TOT * sizeof(float);
    size_t smem_edge = (size_t)SETOT * sizeof(float);
    cudaFuncSetAttribute(k_mlp,  cudaFuncAttributeMaxDynamicSharedMemorySize, (int)smem_mlp);
    cudaFuncSetAttribute(k_edge, cudaFuncAttributeMaxDynamicSharedMemorySize, (int)smem_edge);

    dim3 gG((n + 31) / 32, 32);
    int gMlp  = (e + 31) / 32;
    int gEdge = 592;

    k_w3p<<<(128 * 1024 + T - 1) / T, T>>>(kw3);                 // 1
    k_zero_hist<<<(n + T - 1) / T, T>>>(n);                       // 2
    k_init<<<gn32, T>>>(x, coords, fc1w, fc1b, ei, n, e);         // 3
    k_G<<<gG, 256>>>(n);                                          // 4 <- profiled
    k_scan<<<1, 1024>>>(n);                                       // 5
    k_scatter<<<gE, T>>>(ei, eattr, e);                           // 6
    k_chprep<<<(n + T - 1) / T, T>>>(n);                          // 7
    k_chscan<<<1, 1024>>>(n);                                     // 8
    k_chfill<<<(n + T - 1) / T, T>>>(n);                          // 9

    for (int depth = 0; depth < 3; depth++) {
        if (depth > 0) k_G<<<gG, 256>>>(n);
        k_mlp<<<gMlp, T, smem_mlp>>>(kw1, kb1, kw2, kb2, e);
        k_Bh<<<gn32, T>>>(kb3, n);
        k_edge<<<gEdge, T, smem_edge>>>(cmw1, cmb1, cmw2);
        k_update<<<gn32, T>>>(n);
    }
    k_out<<<(n * 32 + T - 1) / T, T>>>(fw1, fb1, fw2, fb2, dout, n);
}

// round 16
// speedup vs baseline: 1.1488x; 1.1488x over previous
#include <cuda_runtime.h>
#include <cuda_bf16.h>

#define NN 10000
#define EE 100000
#define W  32
#define CHMAX 24576

typedef unsigned long long u64;

__device__ __forceinline__ u64 pk2(float x, float y) {
    u64 r; asm("mov.b64 %0,{%1,%2};" : "=l"(r) : "f"(x), "f"(y)); return r;
}
__device__ __forceinline__ void fma2(u64& d, u64 a, u64 b) {
    asm("fma.rn.f32x2 %0,%1,%2,%0;" : "+l"(d) : "l"(a), "l"(b));
}
__device__ __forceinline__ float2 up2(u64 v) {
    float2 f; asm("mov.b64 {%0,%1},%2;" : "=f"(f.x), "=f"(f.y) : "l"(v)); return f;
}
__device__ __forceinline__ u64 add2(u64 a, u64 b) {
    u64 r; asm("add.rn.f32x2 %0,%1,%2;" : "=l"(r) : "l"(a), "l"(b)); return r;
}

// ---------------- scratch ----------------
__device__ float g_h[NN * W];
__device__ float g_coord[NN * 3];
__device__ float g_G[(size_t)NN * 4096];   // G[n][c*32+i]  (c-major)
__device__ float g_W3p[32 * 4096];         // W3p[j][c*32+i] = ker_w3[c][i*32+j]
__device__ float g_Bh[NN * W];
__device__ float g_msum[NN * W];
__device__ float g_csum[NN * 3];
__device__ int   g_degi[NN];
__device__ int   g_cnt[NN];
__device__ int   g_offs[NN + 1];
__device__ int   g_cur[NN];
__device__ int   g_srow[EE];
__device__ int   g_scol[EE];
__device__ float g_sea[EE * 6];
__device__ float g_k2[(size_t)EE * 128];
__device__ int   g_chcnt[NN];
__device__ int   g_choffs[NN + 1];
__device__ int   g_chv[CHMAX], g_che[CHMAX], g_chc[CHMAX];
__device__ int   g_nch;

// ---------------- setup ----------------

__global__ void k_w3p(const float* __restrict__ kw3) {
    int idx = blockIdx.x * blockDim.x + threadIdx.x;
    if (idx < 128 * 1024) {
        int c = idx >> 10, rem = idx & 1023, i = rem >> 5, j = rem & 31;
        g_W3p[j * 4096 + c * 32 + i] = kw3[idx];
    }
}

__global__ void k_zero_hist(int n) {
    int idx = blockIdx.x * blockDim.x + threadIdx.x;
    if (idx < n) { g_cnt[idx] = 0; g_degi[idx] = 0; }
}

__global__ void k_init(const float* __restrict__ x, const float* __restrict__ coords,
                       const float* __restrict__ fc1w, const float* __restrict__ fc1b,
                       const int* __restrict__ ei, int n, int e) {
    int idx = blockIdx.x * blockDim.x + threadIdx.x;
    if (idx < n * W) {
        int node = idx >> 5, i = idx & 31;
        float acc = fc1b[i];
#pragma unroll
        for (int j = 0; j < 3; j++) acc += x[node * 3 + j] * fc1w[j * W + i];
        g_h[idx] = acc;
    }
    if (idx < n * 3) g_coord[idx] = coords[idx];
    if (idx < e) {
        atomicAdd(&g_cnt[ei[e + idx]], 1);
        atomicAdd(&g_degi[ei[idx]], 1);
    }
}

__global__ __launch_bounds__(1024) void k_scan(int n) {
    __shared__ int ts[1024];
    int tid = threadIdx.x;
    int per = (n + 1023) / 1024;
    int base = tid * per;
    int s = 0;
    for (int i = 0; i < per; i++) { int idx = base + i; if (idx < n) s += g_cnt[idx]; }
    ts[tid] = s;
    __syncthreads();
    for (int off = 1; off < 1024; off <<= 1) {
        int v = (tid >= off) ? ts[tid - off] : 0;
        __syncthreads();
        ts[tid] += v;
        __syncthreads();
    }
    int run = (tid > 0) ? ts[tid - 1] : 0;
    for (int i = 0; i < per; i++) {
        int idx = base + i;
        if (idx < n) { int cv = g_cnt[idx]; g_offs[idx] = run; g_cur[idx] = run; run += cv; }
    }
    if (tid == 1023) g_offs[n] = run;
}

__global__ void k_scatter(const int* __restrict__ ei, const float* __restrict__ ea, int e) {
    int idx = blockIdx.x * blockDim.x + threadIdx.x;
    if (idx >= e) return;
    int c = ei[e + idx];
    int p = atomicAdd(&g_cur[c], 1);
    g_srow[p] = ei[idx];
    g_scol[p] = c;
#pragma unroll
    for (int a = 0; a < 6; a++) g_sea[p * 6 + a] = ea[idx * 6 + a];
}

__global__ void k_chprep(int n) {
    int v = blockIdx.x * blockDim.x + threadIdx.x;
    if (v < n) {
        int d = g_offs[v + 1] - g_offs[v];
        g_chcnt[v] = (d + 7) >> 3;
    }
}

__global__ __launch_bounds__(1024) void k_chscan(int n) {
    __shared__ int ts[1024];
    int tid = threadIdx.x;
    int per = (n + 1023) / 1024;
    int base = tid * per;
    int s = 0;
    for (int i = 0; i < per; i++) { int idx = base + i; if (idx < n) s += g_chcnt[idx]; }
    ts[tid] = s;
    __syncthreads();
    for (int off = 1; off < 1024; off <<= 1) {
        int v = (tid >= off) ? ts[tid - off] : 0;
        __syncthreads();
        ts[tid] += v;
        __syncthreads();
    }
    int run = (tid > 0) ? ts[tid - 1] : 0;
    for (int i = 0; i < per; i++) {
        int idx = base + i;
        if (idx < n) { int cv = g_chcnt[idx]; g_choffs[idx] = run; run += cv; }
    }
    if (tid == 1023) { g_choffs[n] = run; g_nch = run; }
}

__global__ void k_chfill(int n) {
    int v = blockIdx.x * blockDim.x + threadIdx.x;
    if (v >= n) return;
    int base = g_choffs[v], nc = g_chcnt[v];
    int s0 = g_offs[v], d = g_offs[v + 1] - s0;
    for (int k = 0; k < nc; k++) {
        g_chv[base + k] = v;
        g_che[base + k] = s0 + 8 * k;
        int rem = d - 8 * k;
        g_chc[base + k] = rem > 8 ? 8 : rem;
    }
}

// ---------------- per-depth ----------------

// G[n][c*32+i] = h[n][:] @ W3p ; pair-K FFMA2, conflict-free LDS
// tile 64 nodes x 128 cols; thread = 8 nodes x 4 cols (cols 2tx,2tx+1,64+2tx,65+2tx)
__global__ __launch_bounds__(256) void k_G(int n) {
    __shared__ float hs[64 * 32];     // 8KB
    __shared__ u64   bs2[16 * 128];   // 16KB (col-major K-pairs: bs2[j2*128+col])
    const int tid = threadIdx.x;
    const int n0 = blockIdx.x * 64;
    const int q0 = blockIdx.y * 128;
    for (int i = tid; i < 2048; i += 256) {
        int nn = i >> 5, j = i & 31;
        int node = n0 + nn;
        hs[i] = (node < n) ? g_h[node * 32 + j] : 0.0f;
    }
    for (int i = tid; i < 2048; i += 256) {
        int j2 = i >> 7, col = i & 127;
        bs2[i] = pk2(g_W3p[(2 * j2) * 4096 + q0 + col],
                     g_W3p[(2 * j2 + 1) * 4096 + q0 + col]);
    }
    __syncthreads();
    const int ty = tid >> 5, tx = tid & 31;
    const u64 zz = pk2(0.f, 0.f);
    const float* hrow = &hs[ty * 8 * 32];
    u64 acc[8][4];
#pragma unroll
    for (int r = 0; r < 8; r++)
#pragma unroll
        for (int s = 0; s < 4; s++) acc[r][s] = zz;
#pragma unroll 4
    for (int j2 = 0; j2 < 16; j2++) {
        // conflict-free: lane-stride 16B on both
        ulonglong2 bA = *(const ulonglong2*)&bs2[j2 * 128 + 2 * tx];
        ulonglong2 bB = *(const ulonglong2*)&bs2[j2 * 128 + 64 + 2 * tx];
#pragma unroll
        for (int r = 0; r < 8; r++) {
            u64 a2 = *(const u64*)&hrow[r * 32 + 2 * j2];   // broadcast
            fma2(acc[r][0], a2, bA.x);
            fma2(acc[r][1], a2, bA.y);
            fma2(acc[r][2], a2, bB.x);
            fma2(acc[r][3], a2, bB.y);
        }
    }
#pragma unroll
    for (int r = 0; r < 8; r++) {
        int node = n0 + ty * 8 + r;
        if (node < n) {
            float* gout = &g_G[(size_t)node * 4096 + q0];
            float2 o0, o1;
            float2 f0 = up2(acc[r][0]); o0.x = f0.x + f0.y;
            float2 f1 = up2(acc[r][1]); o0.y = f1.x + f1.y;
            float2 f2 = up2(acc[r][2]); o1.x = f2.x + f2.y;
            float2 f3 = up2(acc[r][3]); o1.y = f3.x + f3.y;
            *(float2*)&gout[2 * tx]      = o0;
            *(float2*)&gout[64 + 2 * tx] = o1;
        }
    }
}

// edge MLP (layers 1+2), pair-K FFMA2, conflict-free; 32 edges x 128 outs/block
#define M2W2P 0        // u64[32*128] -> 8192 floats
#define M2K1S 8192     // 32*66 = 2112
#define M2EAS 10304    // 32*9 = 288
#define M2W1S 10592    // 448
#define M2B1S 11040    // 64
#define M2TOT 11104    // *4 = 44416 bytes
__global__ __launch_bounds__(256) void k_mlp(const float* __restrict__ kw1,
                                             const float* __restrict__ kb1,
                                             const float* __restrict__ kw2,
                                             const float* __restrict__ kb2, int e) {
    extern __shared__ float sm[];
    u64* w2p = (u64*)sm;
    const int tid = threadIdx.x;
    const int e0 = blockIdx.x * 32;

    for (int i = tid; i < 4096; i += 256) {
        int j2 = i >> 7, col = i & 127;
        w2p[i] = pk2(kw2[(2 * j2) * 128 + col], kw2[(2 * j2 + 1) * 128 + col]);
    }
    for (int i = tid; i < 448; i += 256) sm[M2W1S + i] = kw1[i];
    if (tid < 64) sm[M2B1S + tid] = kb1[tid];
    for (int i = tid; i < 192; i += 256) {
        int ed = i / 6, a = i - ed * 6;
        sm[M2EAS + ed * 9 + a] = g_sea[(size_t)(e0 + ed) * 6 + a];
    }
    if (tid < 32) {
        int ed = e0 + tid;
        int r = g_srow[ed], c = g_scol[ed];
        float rad = 0.0f;
#pragma unroll
        for (int d = 0; d < 3; d++) {
            float dd = g_coord[r * 3 + d] - g_coord[c * 3 + d];
            rad += dd * dd;
        }
        sm[M2EAS + tid * 9 + 6] = rad;
    }
    __syncthreads();

    // layer 1: 32 edges x 64 outs, 8 outs/thread
    {
        int ed = tid >> 3, q = tid & 7;
        float ea[7];
#pragma unroll
        for (int a = 0; a < 7; a++) ea[a] = sm[M2EAS + ed * 9 + a];
#pragma unroll
        for (int jj = 0; jj < 8; jj++) {
            int c = q * 8 + jj;
            float acc = sm[M2B1S + c];
#pragma unroll
            for (int a = 0; a < 7; a++) acc += ea[a] * sm[M2W1S + a * 64 + c];
            sm[M2K1S + ed * 66 + c] = fmaxf(acc, 0.0f);
        }
    }
    __syncthreads();

    // layer 2: pair-K GEMM 32 edges x 128 cols, K=64; thread = 4 edges x 4 cols
    const int ty = tid >> 5, tx = tid & 31;
    const u64 zz = pk2(0.f, 0.f);
    const float* k1row = &sm[M2K1S + ty * 4 * 66];
    u64 acc[4][4];
#pragma unroll
    for (int r = 0; r < 4; r++)
#pragma unroll
        for (int s = 0; s < 4; s++) acc[r][s] = zz;
#pragma unroll 8
    for (int j2 = 0; j2 < 32; j2++) {
        ulonglong2 bA = *(const ulonglong2*)&w2p[j2 * 128 + 2 * tx];
        ulonglong2 bB = *(const ulonglong2*)&w2p[j2 * 128 + 64 + 2 * tx];
#pragma unroll
        for (int r = 0; r < 4; r++) {
            u64 a2 = *(const u64*)&k1row[r * 66 + 2 * j2];
            fma2(acc[r][0], a2, bA.x);
            fma2(acc[r][1], a2, bA.y);
            fma2(acc[r][2], a2, bB.x);
            fma2(acc[r][3], a2, bB.y);
        }
    }
    float2 bbA = *(const float2*)&kb2[2 * tx];
    float2 bbB = *(const float2*)&kb2[64 + 2 * tx];
#pragma unroll
    for (int r = 0; r < 4; r++) {
        int ed = e0 + ty * 4 + r;
        if (ed < e) {
            float2 o0, o1;
            float2 f0 = up2(acc[r][0]); o0.x = fmaxf(f0.x + f0.y + bbA.x, 0.f);
            float2 f1 = up2(acc[r][1]); o0.y = fmaxf(f1.x + f1.y + bbA.y, 0.f);
            float2 f2 = up2(acc[r][2]); o1.x = fmaxf(f2.x + f2.y + bbB.x, 0.f);
            float2 f3 = up2(acc[r][3]); o1.y = fmaxf(f3.x + f3.y + bbB.y, 0.f);
            float* kout = &g_k2[(size_t)ed * 128];
            *(float2*)&kout[2 * tx]      = o0;
            *(float2*)&kout[64 + 2 * tx] = o1;
        }
    }
}

// Bh + accumulator zeroing fused
__global__ void k_Bh(const float* __restrict__ kb3, int n) {
    int idx = blockIdx.x * blockDim.x + threadIdx.x;
    if (idx < n * 3) g_csum[idx] = 0.0f;
    if (idx >= n * W) return;
    g_msum[idx] = 0.0f;
    int node = idx >> 5, i = idx & 31;
    float acc = 0.0f;
#pragma unroll
    for (int j = 0; j < 32; j++) acc += kb3[i * 32 + j] * g_h[node * 32 + j];
    g_Bh[idx] = acc;
}

// chunked edge kernel: warp per <=8-edge same-col chunk
#define SCM1P 0       // 1024 (cmw1 pairs)
#define SCMB  1024    // 32
#define SCMW  1056    // 32
#define SK2P  1088    // 8 warps * 1024 floats (64 c-pairs x 8 edges as u64)
#define SMSB  9280    // 8 warps * 256
#define SETOT 11328   // *4 = 45312 bytes
__global__ __launch_bounds__(256) void k_edge(const float* __restrict__ cmw1,
                                              const float* __restrict__ cmb1,
                                              const float* __restrict__ cmw2) {
    extern __shared__ float sm[];
    const int tid = threadIdx.x, w = tid >> 5, lane = tid & 31;

    for (int i = tid; i < 1024; i += 256) {
        int i2 = i >> 6, r = i & 63, ln = r >> 1, p = r & 1;
        sm[SCM1P + i] = cmw1[(2 * i2 + p) * 32 + ln];
    }
    if (tid < 32) { sm[SCMB + tid] = cmb1[tid]; sm[SCMW + tid] = cmw2[tid]; }
    __syncthreads();

    u64* K2 = (u64*)(sm + SK2P + w * 1024);   // [c2][s]
    float* msb = sm + SMSB + w * 256;
    const u64 zz = pk2(0.f, 0.f);

    const int TW = gridDim.x * 8;
    const int nch = g_nch;
    for (int ci = blockIdx.x * 8 + w; ci < nch; ci += TW) {
        const int v = g_chv[ci], e0 = g_che[ci], cnt = g_chc[ci];

        {
            int s = lane >> 2, f = lane & 3;
            bool valid = (s < cnt);
#pragma unroll
            for (int t = 0; t < 8; t++) {
                int cb = (t * 4 + f) * 4;
                float4 vv = valid ? *(const float4*)&g_k2[(size_t)(e0 + s) * 128 + cb]
                                  : make_float4(0.f, 0.f, 0.f, 0.f);
                K2[(cb >> 1) * 8 + s]       = pk2(vv.x, vv.y);
                K2[((cb >> 1) + 1) * 8 + s] = pk2(vv.z, vv.w);
            }
        }
        int rl = (lane < cnt) ? g_srow[e0 + lane] : 0;
        float cv = (lane < 3) ? g_coord[v * 3 + lane] : 0.0f;
        float bh = g_Bh[v * 32 + lane];
        __syncwarp();

        const float* gB = g_G + (size_t)v * 4096;
        u64 mm[8];
#pragma unroll
        for (int s = 0; s < 8; s++) mm[s] = zz;
        float ga = gB[lane], gb = gB[32 + lane];
#pragma unroll 4
        for (int c2 = 0; c2 < 64; c2++) {
            u64 gg = pk2(ga, gb);
            if (c2 < 63) { ga = gB[(c2 + 1) * 64 + lane]; gb = gB[(c2 + 1) * 64 + 32 + lane]; }
#pragma unroll
            for (int s = 0; s < 8; s++) fma2(mm[s], K2[c2 * 8 + s], gg);
        }
        float mreg[8];
#pragma unroll
        for (int s = 0; s < 8; s++) {
            float2 f2 = up2(mm[s]);
            mreg[s] = f2.x + f2.y + bh;
            msb[s * 32 + lane] = mreg[s];
        }
        __syncwarp();

        for (int s = 0; s < cnt; s++) {
            u64 ta = zz, tb = zz;
#pragma unroll
            for (int i2 = 0; i2 < 16; i2 += 2) {
                u64 mp0 = *(const u64*)&msb[s * 32 + i2 * 2];
                u64 mp1 = *(const u64*)&msb[s * 32 + i2 * 2 + 2];
                u64 wp0 = *(const u64*)&sm[SCM1P + i2 * 64 + lane * 2];
                u64 wp1 = *(const u64*)&sm[SCM1P + (i2 + 1) * 64 + lane * 2];
                fma2(ta, mp0, wp0);
                fma2(tb, mp1, wp1);
            }
            float2 tf = up2(add2(ta, tb));
            float tac = fmaxf(sm[SCMB + lane] + tf.x + tf.y, 0.0f);
            float ph = tac * sm[SCMW + lane];
#pragma unroll
            for (int o = 16; o; o >>= 1) ph += __shfl_xor_sync(0xffffffffu, ph, o);

            int r = __shfl_sync(0xffffffffu, rl, s);
            atomicAdd(&g_msum[r * 32 + lane], mreg[s]);
            if (lane < 3) {
                float cdl = g_coord[r * 3 + lane] - cv;
                atomicAdd(&g_csum[r * 3 + lane], cdl * ph);
            }
        }
        __syncwarp();
    }
}

__global__ void k_update(int n) {
    int idx = blockIdx.x * blockDim.x + threadIdx.x;
    if (idx >= n * W) return;
    int node = idx >> 5, i = idx & 31;
    int d = g_degi[node];
    float inv = 1.0f / (float)(d > 1 ? d : 1);
    g_h[idx] = fmaxf(g_h[idx] + g_msum[idx] * inv, 0.0f);
    if (i < 3) g_coord[node * 3 + i] += g_csum[node * 3 + i] * inv;
}

__global__ __launch_bounds__(256) void k_out(const float* __restrict__ fw1,
                                             const float* __restrict__ fb1,
                                             const float* __restrict__ fw2,
                                             const float* __restrict__ fb2,
                                             float* __restrict__ dout, int n) {
    int gw = (blockIdx.x * blockDim.x + threadIdx.x) >> 5;
    int lane = threadIdx.x & 31;
    if (gw >= n) return;
    const int node = gw;
    float hm = g_h[node * 32 + lane];
    float t0 = fb1[lane], t1 = fb1[lane + 32];
#pragma unroll
    for (int i = 0; i < 32; i++) {
        float hh = __shfl_sync(0xffffffffu, hm, i);
        t0 += hh * fw1[i * 64 + lane];
        t1 += hh * fw1[i * 64 + lane + 32];
    }
    t0 = fmaxf(t0, 0.0f);
    t1 = fmaxf(t1, 0.0f);
    float part = t0 * fw2[lane] + t1 * fw2[32 + lane];
#pragma unroll
    for (int o = 16; o; o >>= 1) part += __shfl_xor_sync(0xffffffffu, part, o);
    if (lane == 0) dout[node] = part + fb2[0];
    if (lane < 3) dout[n + node * 3 + lane] = g_coord[node * 3 + lane];
}

// ---------------- host launcher ----------------
extern "C" void kernel_launch(void* const* d_in, const int* in_sizes, int n_in,
                              void* d_out, int out_size) {
    const float* x      = (const float*)d_in[0];
    const int*   ei     = (const int*)  d_in[1];
    const float* eattr  = (const float*)d_in[2];
    const float* coords = (const float*)d_in[3];
    const float* fc1w   = (const float*)d_in[4];
    const float* fc1b   = (const float*)d_in[5];
    const float* kw1    = (const float*)d_in[6];
    const float* kb1    = (const float*)d_in[7];
    const float* kw2    = (const float*)d_in[8];
    const float* kb2    = (const float*)d_in[9];
    const float* kw3    = (const float*)d_in[10];
    const float* kb3    = (const float*)d_in[11];
    const float* cmw1   = (const float*)d_in[12];
    const float* cmb1   = (const float*)d_in[13];
    const float* cmw2   = (const float*)d_in[14];
    const float* fw1    = (const float*)d_in[15];
    const float* fb1    = (const float*)d_in[16];
    const float* fw2    = (const float*)d_in[17];
    const float* fb2    = (const float*)d_in[18];
    float* dout = (float*)d_out;

    int n = in_sizes[0] / 3;   // 10000
    int e = in_sizes[1] / 2;   // 100000
    if (n > NN) n = NN;
    if (e > EE) e = EE;

    const int T = 256;
    int gn32 = (n * W + T - 1) / T;
    int gE   = (e + T - 1) / T;
    size_t smem_mlp  = (size_t)M2TOT * sizeof(float);
    size_t smem_edge = (size_t)SETOT * sizeof(float);
    cudaFuncSetAttribute(k_mlp,  cudaFuncAttributeMaxDynamicSharedMemorySize, (int)smem_mlp);
    cudaFuncSetAttribute(k_edge, cudaFuncAttributeMaxDynamicSharedMemorySize, (int)smem_edge);

    dim3 gG((n + 63) / 64, 32);
    int gMlp  = (e + 31) / 32;
    int gEdge = 592;

    k_w3p<<<(128 * 1024 + T - 1) / T, T>>>(kw3);                 // 1
    k_zero_hist<<<(n + T - 1) / T, T>>>(n);                       // 2
    k_init<<<gn32, T>>>(x, coords, fc1w, fc1b, ei, n, e);         // 3
    k_G<<<gG, 256>>>(n);                                          // 4 <- profiled
    k_scan<<<1, 1024>>>(n);                                       // 5
    k_scatter<<<gE, T>>>(ei, eattr, e);                           // 6
    k_chprep<<<(n + T - 1) / T, T>>>(n);                          // 7
    k_chscan<<<1, 1024>>>(n);                                     // 8
    k_chfill<<<(n + T - 1) / T, T>>>(n);                          // 9

    for (int depth = 0; depth < 3; depth++) {
        if (depth > 0) k_G<<<gG, 256>>>(n);
        k_mlp<<<gMlp, T, smem_mlp>>>(kw1, kb1, kw2, kb2, e);
        k_Bh<<<gn32, T>>>(kb3, n);
        k_edge<<<gEdge, T, smem_edge>>>(cmw1, cmb1, cmw2);
        k_update<<<gn32, T>>>(n);
    }
    k_out<<<(n * 32 + T - 1) / T, T>>>(fw1, fb1, fw2, fb2, dout, n);
}